// round 3
// baseline (speedup 1.0000x reference)
#include <cuda_runtime.h>

#define MAXN  100000
#define MAXE  3200000
#define HD    64
#define NG    512
#define NC    10

// ---------------- scratch (device globals; 16B-aligned via float4) ----------
__device__ int    g_deg[MAXN];
__device__ float  g_snorm[MAXN];          // dis*dis (self-loop norm)
__device__ float  g_dis[MAXN];            // 1/sqrt(deg+1)
__device__ float  g_enorm[MAXE];          // dis[src]*dis[dst]
__device__ float4 g_bufA[MAXN * HD / 4];  // 16B aligned
__device__ float4 g_bufB[MAXN * HD / 4];
__device__ float4 g_agg [MAXN * HD / 4];
__device__ float4 g_pool[NG * HD / 4];
__device__ float  g_cnt [NG];

// ---------------- helpers ---------------------------------------------------
__device__ __forceinline__ void red_add_v4(float4* p, float4 v) {
    asm volatile("red.global.add.v4.f32 [%0], {%1,%2,%3,%4};"
                 :: "l"(p), "f"(v.x), "f"(v.y), "f"(v.z), "f"(v.w)
                 : "memory");
}

// ---------------- kernels ---------------------------------------------------
__global__ void deg_count(const int* __restrict__ dst, int* __restrict__ deg,
                          int E) {
    int e = blockIdx.x * blockDim.x + threadIdx.x;
    if (e < E) atomicAdd(&deg[dst[e]], 1);
}

__global__ void node_norms(const int* __restrict__ deg, float* __restrict__ dis,
                           float* __restrict__ snorm, int N) {
    int i = blockIdx.x * blockDim.x + threadIdx.x;
    if (i < N) {
        float d = rsqrtf((float)deg[i] + 1.0f);
        dis[i] = d;
        snorm[i] = d * d;
    }
}

__global__ void edge_norms(const int* __restrict__ src,
                           const int* __restrict__ dst,
                           const float* __restrict__ dis,
                           float* __restrict__ enorm, int E) {
    int e = blockIdx.x * blockDim.x + threadIdx.x;
    if (e < E) enorm[e] = dis[src[e]] * dis[dst[e]];
}

// h[N, HD] = in[N, K] @ W[K, HD]  (W cached in shared)
template <int K>
__global__ __launch_bounds__(512)
void gemm64(const float* __restrict__ in, const float* __restrict__ W,
            float* __restrict__ out, int N) {
    __shared__ float sW[K * HD];
    for (int i = threadIdx.y * HD + threadIdx.x; i < K * HD; i += 512)
        sW[i] = W[i];
    __syncthreads();
    int row = blockIdx.x * 8 + threadIdx.y;
    if (row >= N) return;
    int col = threadIdx.x;
    const float* xr = in + (size_t)row * K;
    float acc = 0.f;
#pragma unroll 8
    for (int k = 0; k < K; k++)
        acc = fmaf(__ldg(&xr[k]), sW[k * HD + col], acc);
    out[(size_t)row * HD + col] = acc;
}

// per (edge, 16B-chunk): agg[dst] += h[src] * enorm[e]
__global__ void scatter_edges(const int* __restrict__ src,
                              const int* __restrict__ dst,
                              const float* __restrict__ enorm,
                              const float4* __restrict__ h4,
                              float4* __restrict__ agg4, int E) {
    long long idx = blockIdx.x * (long long)blockDim.x + threadIdx.x;
    long long total = (long long)E * 16;
    if (idx >= total) return;
    int e = (int)(idx >> 4);
    int c = (int)(idx & 15);
    int s = src[e];
    int d = dst[e];
    float n = __ldg(&enorm[e]);
    float4 v = h4[(long long)s * 16 + c];
    float4 r = make_float4(v.x * n, v.y * n, v.z * n, v.w * n);
    red_add_v4(&agg4[(long long)d * 16 + c], r);
}

// h = agg + h * snorm + b   (optionally relu); in place into h4
__global__ void finalize_layer(const float4* __restrict__ agg4,
                               const float* __restrict__ snorm,
                               const float* __restrict__ bias,
                               float4* __restrict__ h4, int N, int do_relu) {
    long long idx = blockIdx.x * (long long)blockDim.x + threadIdx.x;
    if (idx >= (long long)N * 16) return;
    int i = (int)(idx >> 4);
    int c = (int)(idx & 15);
    float s = snorm[i];
    float4 a = agg4[idx];
    float4 h = h4[idx];
    const float4* b4 = (const float4*)bias;   // harness buffers are 256B aligned
    float4 b = b4[c];
    float4 o;
    o.x = fmaf(h.x, s, a.x) + b.x;
    o.y = fmaf(h.y, s, a.y) + b.y;
    o.z = fmaf(h.z, s, a.z) + b.z;
    o.w = fmaf(h.w, s, a.w) + b.w;
    if (do_relu) {
        o.x = fmaxf(o.x, 0.f); o.y = fmaxf(o.y, 0.f);
        o.z = fmaxf(o.z, 0.f); o.w = fmaxf(o.w, 0.f);
    }
    h4[idx] = o;
}

__global__ void pool_sum(const float4* __restrict__ h4,
                         const int* __restrict__ batch,
                         float4* __restrict__ pool4, int N) {
    long long idx = blockIdx.x * (long long)blockDim.x + threadIdx.x;
    if (idx >= (long long)N * 16) return;
    int i = (int)(idx >> 4);
    int c = (int)(idx & 15);
    int g = batch[i];
    red_add_v4(&pool4[(long long)g * 16 + c], h4[idx]);
}

__global__ void pool_cnt(const int* __restrict__ batch,
                         float* __restrict__ cnt, int N) {
    int i = blockIdx.x * blockDim.x + threadIdx.x;
    if (i < N) atomicAdd(&cnt[batch[i]], 1.0f);
}

__global__ void fc_kernel(const float* __restrict__ pool,
                          const float* __restrict__ cnt,
                          const float* __restrict__ Wfc,
                          const float* __restrict__ bfc,
                          float* __restrict__ out) {
    int b = blockIdx.x;
    int t = threadIdx.x;           // 64 threads
    __shared__ float p[HD];
    float inv = 1.0f / fmaxf(cnt[b], 1.0f);
    p[t] = pool[b * HD + t] * inv;
    __syncthreads();
    if (t < NC) {
        float acc = bfc[t];
#pragma unroll
        for (int h = 0; h < HD; h++)
            acc = fmaf(p[h], Wfc[h * NC + t], acc);
        out[b * NC + t] = acc;
    }
}

// ---------------- launch -----------------------------------------------------
extern "C" void kernel_launch(void* const* d_in, const int* in_sizes, int n_in,
                              void* d_out, int out_size) {
    const float* x     = (const float*)d_in[0];
    const int*   ei    = (const int*)d_in[1];     // int32! (JAX x64 disabled)
    const int*   batch = (const int*)d_in[2];
    const float* W1    = (const float*)d_in[3];
    const float* b1    = (const float*)d_in[4];
    const float* W2    = (const float*)d_in[5];
    const float* b2    = (const float*)d_in[6];
    const float* W3    = (const float*)d_in[7];
    const float* b3    = (const float*)d_in[8];
    const float* Wfc   = (const float*)d_in[9];
    const float* bfc   = (const float*)d_in[10];
    float*       out   = (float*)d_out;

    int N = in_sizes[0] / 128;
    int E = in_sizes[1] / 2;
    int B = out_size / NC;

    const int* src = ei;
    const int* dst = ei + E;

    void *p_deg, *p_dis, *p_snorm, *p_enorm, *p_A, *p_B, *p_agg, *p_pool, *p_cnt;
    cudaGetSymbolAddress(&p_deg, g_deg);
    cudaGetSymbolAddress(&p_dis, g_dis);
    cudaGetSymbolAddress(&p_snorm, g_snorm);
    cudaGetSymbolAddress(&p_enorm, g_enorm);
    cudaGetSymbolAddress(&p_A, g_bufA);
    cudaGetSymbolAddress(&p_B, g_bufB);
    cudaGetSymbolAddress(&p_agg, g_agg);
    cudaGetSymbolAddress(&p_pool, g_pool);
    cudaGetSymbolAddress(&p_cnt, g_cnt);

    int*    deg   = (int*)p_deg;
    float*  dis   = (float*)p_dis;
    float*  snorm = (float*)p_snorm;
    float*  enorm = (float*)p_enorm;
    float4* A4    = (float4*)p_A;
    float4* B4    = (float4*)p_B;
    float4* agg4  = (float4*)p_agg;
    float4* pool4 = (float4*)p_pool;
    float*  cnt   = (float*)p_cnt;
    float*  A     = (float*)p_A;
    float*  Bb    = (float*)p_B;
    float*  pool  = (float*)p_pool;

    const int T = 256;
    long long EC  = (long long)E * 16;   // edge 16B-chunks
    long long NC4 = (long long)N * 16;   // node 16B-chunks
    unsigned gE  = (unsigned)((EC + T - 1) / T);
    unsigned gN4 = (unsigned)((NC4 + T - 1) / T);

    // ---- norms ----
    cudaMemsetAsync(deg, 0, (size_t)N * sizeof(int));
    deg_count<<<(E + T - 1) / T, T>>>(dst, deg, E);
    node_norms<<<(N + T - 1) / T, T>>>(deg, dis, snorm, N);
    edge_norms<<<(E + T - 1) / T, T>>>(src, dst, dis, enorm, E);

    dim3 gblk(64, 8);

    // ---- layer 1: x(128) -> A ----
    gemm64<128><<<(N + 7) / 8, gblk>>>(x, W1, A, N);
    cudaMemsetAsync(agg4, 0, (size_t)N * HD * sizeof(float));
    scatter_edges<<<gE, T>>>(src, dst, enorm, A4, agg4, E);
    finalize_layer<<<gN4, T>>>(agg4, snorm, b1, A4, N, 1);

    // ---- layer 2: A -> B ----
    gemm64<64><<<(N + 7) / 8, gblk>>>(A, W2, Bb, N);
    cudaMemsetAsync(agg4, 0, (size_t)N * HD * sizeof(float));
    scatter_edges<<<gE, T>>>(src, dst, enorm, B4, agg4, E);
    finalize_layer<<<gN4, T>>>(agg4, snorm, b2, B4, N, 1);

    // ---- layer 3: B -> A ----
    gemm64<64><<<(N + 7) / 8, gblk>>>(Bb, W3, A, N);
    cudaMemsetAsync(agg4, 0, (size_t)N * HD * sizeof(float));
    scatter_edges<<<gE, T>>>(src, dst, enorm, A4, agg4, E);
    finalize_layer<<<gN4, T>>>(agg4, snorm, b3, A4, N, 0);

    // ---- pool + fc ----
    cudaMemsetAsync(pool4, 0, (size_t)B * HD * sizeof(float));
    cudaMemsetAsync(cnt, 0, (size_t)B * sizeof(float));
    pool_sum<<<gN4, T>>>(A4, batch, pool4, N);
    pool_cnt<<<(N + T - 1) / T, T>>>(batch, cnt, N);
    fc_kernel<<<B, HD>>>(pool, cnt, Wfc, bfc, out);
}

// round 4
// speedup vs baseline: 2.3092x; 2.3092x over previous
#include <cuda_runtime.h>

#define MAXN  100000
#define MAXE  3200000
#define HD    64
#define NG    512
#define NC    10

// ---------------- scratch (device globals) ----------------------------------
__device__ int    g_deg[MAXN];
__device__ int    g_cur[MAXN];
__device__ int    g_off[MAXN + 1];
__device__ float  g_snorm[MAXN];            // dis*dis (self-loop norm)
__device__ float  g_dis[MAXN];              // 1/sqrt(deg+1)
__device__ int    g_srcs[MAXE];             // src ids, CSR-sorted by dst
__device__ float  g_ens [MAXE];             // edge norms, CSR-sorted by dst
__device__ float4 g_bufA[MAXN * HD / 4];
__device__ float4 g_bufB[MAXN * HD / 4];
__device__ float4 g_pool[NG * HD / 4];
__device__ float  g_cnt [NG];

// ---------------- helpers ---------------------------------------------------
__device__ __forceinline__ void red_add_v4(float4* p, float4 v) {
    asm volatile("red.global.add.v4.f32 [%0], {%1,%2,%3,%4};"
                 :: "l"(p), "f"(v.x), "f"(v.y), "f"(v.z), "f"(v.w)
                 : "memory");
}

// ---------------- CSR build --------------------------------------------------
__global__ void deg_count(const int* __restrict__ dst, int* __restrict__ deg,
                          int E) {
    int e = blockIdx.x * blockDim.x + threadIdx.x;
    if (e < E) atomicAdd(&deg[dst[e]], 1);
}

__global__ void node_norms(const int* __restrict__ deg, float* __restrict__ dis,
                           float* __restrict__ snorm, int N) {
    int i = blockIdx.x * blockDim.x + threadIdx.x;
    if (i < N) {
        float d = rsqrtf((float)deg[i] + 1.0f);
        dis[i] = d;
        snorm[i] = d * d;
    }
}

// single-block exclusive scan (warp-shuffle based), deg[0..N) -> off[0..N]
__global__ void exscan_kernel(const int* __restrict__ deg,
                              int* __restrict__ off, int N) {
    __shared__ int warp_pre[32];
    __shared__ int s_carry, s_total;
    int tid  = threadIdx.x;           // 1024 threads
    int lane = tid & 31, wid = tid >> 5;
    if (tid == 0) s_carry = 0;
    __syncthreads();
    for (int base = 0; base < N; base += 1024) {
        int i = base + tid;
        int v = (i < N) ? deg[i] : 0;
        int incl = v;
#pragma unroll
        for (int o = 1; o < 32; o <<= 1) {
            int t = __shfl_up_sync(~0u, incl, o);
            if (lane >= o) incl += t;
        }
        if (lane == 31) warp_pre[wid] = incl;
        __syncthreads();
        if (wid == 0) {
            int w = warp_pre[lane];
            int wincl = w;
#pragma unroll
            for (int o = 1; o < 32; o <<= 1) {
                int t = __shfl_up_sync(~0u, wincl, o);
                if (lane >= o) wincl += t;
            }
            warp_pre[lane] = wincl - w;          // exclusive warp prefix
            if (lane == 31) s_total = wincl;     // chunk total
        }
        __syncthreads();
        if (i < N) off[i] = s_carry + warp_pre[wid] + incl - v;
        __syncthreads();
        if (tid == 0) s_carry += s_total;
        __syncthreads();
    }
    if (threadIdx.x == 0) off[N] = s_carry;
}

__global__ void permute_edges(const int* __restrict__ src,
                              const int* __restrict__ dst,
                              const float* __restrict__ dis,
                              const int* __restrict__ off,
                              int* __restrict__ cur,
                              int* __restrict__ srcs,
                              float* __restrict__ ens, int E) {
    int e = blockIdx.x * blockDim.x + threadIdx.x;
    if (e >= E) return;
    int s = src[e], d = dst[e];
    int p = off[d] + atomicAdd(&cur[d], 1);
    srcs[p] = s;
    ens[p]  = dis[s] * dis[d];
}

// ---------------- GEMM: out[N,64] = in[N,K] @ W[K,64] -----------------------
// 64x64 block tile, 256 threads, 4x4 register tile per thread.
template <int K>
__global__ __launch_bounds__(256)
void gemm_tile(const float* __restrict__ in, const float* __restrict__ W,
               float* __restrict__ out, int N) {
    __shared__ float sx[64 * 36];   // padded stride 36 (bank-conflict free)
    __shared__ float sw[32 * 64];
    int tid = threadIdx.x;
    int tx = tid & 15, ty = tid >> 4;
    int row0 = blockIdx.x * 64;
    float acc[4][4] = {};
    for (int kc = 0; kc < K; kc += 32) {
#pragma unroll
        for (int i = 0; i < 2; i++) {           // x chunk: 64 rows x 32 k
            int t = tid + i * 256;              // 512 float4 slots
            int r = t >> 3, c4 = t & 7;
            int grow = row0 + r;
            float4 v = make_float4(0.f, 0.f, 0.f, 0.f);
            if (grow < N)
                v = *(const float4*)&in[(size_t)grow * K + kc + c4 * 4];
            *(float4*)&sx[r * 36 + c4 * 4] = v;
        }
#pragma unroll
        for (int i = 0; i < 2; i++) {           // W chunk: 32 k x 64 cols
            int t = tid + i * 256;
            int k = t >> 4, c4 = t & 15;
            *(float4*)&sw[k * 64 + c4 * 4] =
                *(const float4*)&W[(size_t)(kc + k) * 64 + c4 * 4];
        }
        __syncthreads();
#pragma unroll
        for (int k = 0; k < 32; k++) {
            float4 b = *(float4*)&sw[k * 64 + tx * 4];
            float a0 = sx[(ty * 4 + 0) * 36 + k];
            float a1 = sx[(ty * 4 + 1) * 36 + k];
            float a2 = sx[(ty * 4 + 2) * 36 + k];
            float a3 = sx[(ty * 4 + 3) * 36 + k];
            acc[0][0] = fmaf(a0, b.x, acc[0][0]);
            acc[0][1] = fmaf(a0, b.y, acc[0][1]);
            acc[0][2] = fmaf(a0, b.z, acc[0][2]);
            acc[0][3] = fmaf(a0, b.w, acc[0][3]);
            acc[1][0] = fmaf(a1, b.x, acc[1][0]);
            acc[1][1] = fmaf(a1, b.y, acc[1][1]);
            acc[1][2] = fmaf(a1, b.z, acc[1][2]);
            acc[1][3] = fmaf(a1, b.w, acc[1][3]);
            acc[2][0] = fmaf(a2, b.x, acc[2][0]);
            acc[2][1] = fmaf(a2, b.y, acc[2][1]);
            acc[2][2] = fmaf(a2, b.z, acc[2][2]);
            acc[2][3] = fmaf(a2, b.w, acc[2][3]);
            acc[3][0] = fmaf(a3, b.x, acc[3][0]);
            acc[3][1] = fmaf(a3, b.y, acc[3][1]);
            acc[3][2] = fmaf(a3, b.z, acc[3][2]);
            acc[3][3] = fmaf(a3, b.w, acc[3][3]);
        }
        __syncthreads();
    }
#pragma unroll
    for (int i = 0; i < 4; i++) {
        int grow = row0 + ty * 4 + i;
        if (grow < N)
            *(float4*)&out[(size_t)grow * 64 + tx * 4] =
                make_float4(acc[i][0], acc[i][1], acc[i][2], acc[i][3]);
    }
}

// ---------------- fused CSR gather + self-loop + bias + relu -----------------
// one warp per dst node; lane owns 2 feature columns (float2)
__global__ __launch_bounds__(256)
void gather_csr(const int* __restrict__ off, const int* __restrict__ srcs,
                const float* __restrict__ ens, const float* __restrict__ hin,
                float* __restrict__ hout, const float* __restrict__ snorm,
                const float* __restrict__ bias, int N, int do_relu) {
    int w = (blockIdx.x * blockDim.x + threadIdx.x) >> 5;
    int lane = threadIdx.x & 31;
    if (w >= N) return;
    const float2* h2 = (const float2*)hin;
    int s = off[w], e = off[w + 1];
    float sn = snorm[w];
    float2 self = h2[(size_t)w * 32 + lane];
    float ax = self.x * sn, ay = self.y * sn;
    int i = s;
    for (; i + 2 <= e; i += 2) {
        int u0 = srcs[i], u1 = srcs[i + 1];
        float n0 = ens[i], n1 = ens[i + 1];
        float2 v0 = h2[(size_t)u0 * 32 + lane];
        float2 v1 = h2[(size_t)u1 * 32 + lane];
        ax = fmaf(v0.x, n0, ax); ay = fmaf(v0.y, n0, ay);
        ax = fmaf(v1.x, n1, ax); ay = fmaf(v1.y, n1, ay);
    }
    if (i < e) {
        int u = srcs[i]; float n = ens[i];
        float2 v = h2[(size_t)u * 32 + lane];
        ax = fmaf(v.x, n, ax); ay = fmaf(v.y, n, ay);
    }
    float2 b = ((const float2*)bias)[lane];
    ax += b.x; ay += b.y;
    if (do_relu) { ax = fmaxf(ax, 0.f); ay = fmaxf(ay, 0.f); }
    ((float2*)hout)[(size_t)w * 32 + lane] = make_float2(ax, ay);
}

// ---------------- pooling + FC -----------------------------------------------
__global__ void pool_sum(const float4* __restrict__ h4,
                         const int* __restrict__ batch,
                         float4* __restrict__ pool4, int N) {
    long long idx = blockIdx.x * (long long)blockDim.x + threadIdx.x;
    if (idx >= (long long)N * 16) return;
    int i = (int)(idx >> 4);
    int c = (int)(idx & 15);
    int g = batch[i];
    float4 v = h4[idx];
    red_add_v4(&pool4[(long long)g * 16 + c], v);
}

__global__ void pool_cnt(const int* __restrict__ batch,
                         float* __restrict__ cnt, int N) {
    int i = blockIdx.x * blockDim.x + threadIdx.x;
    if (i < N) atomicAdd(&cnt[batch[i]], 1.0f);
}

__global__ void fc_kernel(const float* __restrict__ pool,
                          const float* __restrict__ cnt,
                          const float* __restrict__ Wfc,
                          const float* __restrict__ bfc,
                          float* __restrict__ out) {
    int b = blockIdx.x;
    int t = threadIdx.x;           // 64 threads
    __shared__ float p[HD];
    float inv = 1.0f / fmaxf(cnt[b], 1.0f);
    p[t] = pool[b * HD + t] * inv;
    __syncthreads();
    if (t < NC) {
        float acc = bfc[t];
#pragma unroll
        for (int h = 0; h < HD; h++)
            acc = fmaf(p[h], Wfc[h * NC + t], acc);
        out[b * NC + t] = acc;
    }
}

// ---------------- launch -----------------------------------------------------
extern "C" void kernel_launch(void* const* d_in, const int* in_sizes, int n_in,
                              void* d_out, int out_size) {
    const float* x     = (const float*)d_in[0];
    const int*   ei    = (const int*)d_in[1];     // int32 (JAX x64 disabled)
    const int*   batch = (const int*)d_in[2];
    const float* W1    = (const float*)d_in[3];
    const float* b1    = (const float*)d_in[4];
    const float* W2    = (const float*)d_in[5];
    const float* b2    = (const float*)d_in[6];
    const float* W3    = (const float*)d_in[7];
    const float* b3    = (const float*)d_in[8];
    const float* Wfc   = (const float*)d_in[9];
    const float* bfc   = (const float*)d_in[10];
    float*       out   = (float*)d_out;

    int N = in_sizes[0] / 128;
    int E = in_sizes[1] / 2;
    int B = out_size / NC;

    const int* src = ei;
    const int* dst = ei + E;

    void *p_deg, *p_cur, *p_off, *p_dis, *p_snorm, *p_srcs, *p_ens,
         *p_A, *p_B, *p_pool, *p_cnt;
    cudaGetSymbolAddress(&p_deg, g_deg);
    cudaGetSymbolAddress(&p_cur, g_cur);
    cudaGetSymbolAddress(&p_off, g_off);
    cudaGetSymbolAddress(&p_dis, g_dis);
    cudaGetSymbolAddress(&p_snorm, g_snorm);
    cudaGetSymbolAddress(&p_srcs, g_srcs);
    cudaGetSymbolAddress(&p_ens, g_ens);
    cudaGetSymbolAddress(&p_A, g_bufA);
    cudaGetSymbolAddress(&p_B, g_bufB);
    cudaGetSymbolAddress(&p_pool, g_pool);
    cudaGetSymbolAddress(&p_cnt, g_cnt);

    int*    deg   = (int*)p_deg;
    int*    cur   = (int*)p_cur;
    int*    off   = (int*)p_off;
    float*  dis   = (float*)p_dis;
    float*  snorm = (float*)p_snorm;
    int*    srcs  = (int*)p_srcs;
    float*  ens   = (float*)p_ens;
    float*  A     = (float*)p_A;
    float*  Bb    = (float*)p_B;
    float4* B4    = (float4*)p_B;
    float4* pool4 = (float4*)p_pool;
    float*  pool  = (float*)p_pool;
    float*  cnt   = (float*)p_cnt;

    const int T = 256;
    int gEdge = (E + T - 1) / T;
    int gNode = (N + T - 1) / T;
    int gWarp = (int)(((long long)N * 32 + T - 1) / T);   // warp-per-node grids
    int gGemm = (N + 63) / 64;

    // ---- CSR build + norms ----
    cudaMemsetAsync(deg, 0, (size_t)N * sizeof(int));
    cudaMemsetAsync(cur, 0, (size_t)N * sizeof(int));
    deg_count<<<gEdge, T>>>(dst, deg, E);
    node_norms<<<gNode, T>>>(deg, dis, snorm, N);
    exscan_kernel<<<1, 1024>>>(deg, off, N);
    permute_edges<<<gEdge, T>>>(src, dst, dis, off, cur, srcs, ens, E);

    // ---- layer 1: x(128) -> A -> B ----
    gemm_tile<128><<<gGemm, T>>>(x, W1, A, N);
    gather_csr<<<gWarp, T>>>(off, srcs, ens, A, Bb, snorm, b1, N, 1);

    // ---- layer 2: B -> A -> B ----
    gemm_tile<64><<<gGemm, T>>>(Bb, W2, A, N);
    gather_csr<<<gWarp, T>>>(off, srcs, ens, A, Bb, snorm, b2, N, 1);

    // ---- layer 3: B -> A -> B ----
    gemm_tile<64><<<gGemm, T>>>(Bb, W3, A, N);
    gather_csr<<<gWarp, T>>>(off, srcs, ens, A, Bb, snorm, b3, N, 0);

    // ---- pool + fc ----
    cudaMemsetAsync(pool4, 0, (size_t)B * HD * sizeof(float));
    cudaMemsetAsync(cnt, 0, (size_t)B * sizeof(float));
    pool_sum<<<(int)(((long long)N * 16 + T - 1) / T), T>>>(B4, batch, pool4, N);
    pool_cnt<<<gNode, T>>>(batch, cnt, N);
    fc_kernel<<<B, HD>>>(pool, cnt, Wfc, bfc, out);
}

// round 5
// speedup vs baseline: 2.7185x; 1.1772x over previous
#include <cuda_runtime.h>

#define MAXN  100000
#define MAXE  3200000
#define HD    64
#define NG    512
#define NC    10
#define SCANB 1024
#define MAXBLK 128   // ceil(MAXN/SCANB) = 98

// ---------------- scratch (device globals) ----------------------------------
__device__ int    g_deg[MAXN];
__device__ int    g_cur[MAXN];
__device__ int    g_off[MAXN + 1];
__device__ int    g_blksum[MAXBLK];
__device__ int    g_blkoff[MAXBLK];
__device__ float  g_snorm[MAXN];            // dis*dis (self-loop norm)
__device__ float  g_dis[MAXN];              // 1/sqrt(deg+1)
__device__ int    g_srcs[MAXE];             // src ids, CSR-sorted by dst
__device__ float4 g_bufA[MAXN * HD / 4];
__device__ float4 g_bufB[MAXN * HD / 4];
__device__ float4 g_pool[NG * HD / 4];
__device__ float  g_cnt [NG];

// ---------------- helpers ---------------------------------------------------
__device__ __forceinline__ void red_add_v4(float4* p, float4 v) {
    asm volatile("red.global.add.v4.f32 [%0], {%1,%2,%3,%4};"
                 :: "l"(p), "f"(v.x), "f"(v.y), "f"(v.z), "f"(v.w)
                 : "memory");
}

// ---------------- CSR build --------------------------------------------------
__global__ void deg_count(const int* __restrict__ dst, int* __restrict__ deg,
                          int E) {
    int e = blockIdx.x * blockDim.x + threadIdx.x;
    if (e < E) atomicAdd(&deg[dst[e]], 1);
}

__global__ void node_norms(const int* __restrict__ deg, float* __restrict__ dis,
                           float* __restrict__ snorm, int N) {
    int i = blockIdx.x * blockDim.x + threadIdx.x;
    if (i < N) {
        float d = rsqrtf((float)deg[i] + 1.0f);
        dis[i] = d;
        snorm[i] = d * d;
    }
}

// ---- 3-phase parallel exclusive scan of deg[0..N) into off[0..N] ----
__global__ void scan_p1_reduce(const int* __restrict__ deg,
                               int* __restrict__ blksum, int N) {
    __shared__ int ws[32];
    int i = blockIdx.x * SCANB + threadIdx.x;
    int v = (i < N) ? deg[i] : 0;
    int lane = threadIdx.x & 31, wid = threadIdx.x >> 5;
#pragma unroll
    for (int o = 16; o > 0; o >>= 1) v += __shfl_down_sync(~0u, v, o);
    if (lane == 0) ws[wid] = v;
    __syncthreads();
    if (wid == 0) {
        int t = ws[lane];
#pragma unroll
        for (int o = 16; o > 0; o >>= 1) t += __shfl_down_sync(~0u, t, o);
        if (lane == 0) blksum[blockIdx.x] = t;
    }
}

__global__ void scan_p2_blk(const int* __restrict__ blksum,
                            int* __restrict__ blkoff,
                            int* __restrict__ off, int nblk, int N) {
    __shared__ int s[MAXBLK];
    int t = threadIdx.x;                        // MAXBLK threads
    s[t] = (t < nblk) ? blksum[t] : 0;
    __syncthreads();
#pragma unroll
    for (int o = 1; o < MAXBLK; o <<= 1) {      // Hillis-Steele inclusive
        int v = (t >= o) ? s[t - o] : 0;
        __syncthreads();
        s[t] += v;
        __syncthreads();
    }
    if (t < nblk) blkoff[t] = s[t] - blksum[t]; // exclusive
    if (t == nblk - 1) off[N] = s[t];           // total
}

__global__ void scan_p3_scanadd(const int* __restrict__ deg,
                                const int* __restrict__ blkoff,
                                int* __restrict__ off, int N) {
    __shared__ int wpre[32];
    int i = blockIdx.x * SCANB + threadIdx.x;
    int v = (i < N) ? deg[i] : 0;
    int lane = threadIdx.x & 31, wid = threadIdx.x >> 5;
    int incl = v;
#pragma unroll
    for (int o = 1; o < 32; o <<= 1) {
        int t = __shfl_up_sync(~0u, incl, o);
        if (lane >= o) incl += t;
    }
    if (lane == 31) wpre[wid] = incl;
    __syncthreads();
    if (wid == 0) {
        int w = wpre[lane];
        int wincl = w;
#pragma unroll
        for (int o = 1; o < 32; o <<= 1) {
            int t = __shfl_up_sync(~0u, wincl, o);
            if (lane >= o) wincl += t;
        }
        wpre[lane] = wincl - w;
    }
    __syncthreads();
    if (i < N) off[i] = blkoff[blockIdx.x] + wpre[wid] + incl - v;
}

__global__ void permute_edges(const int* __restrict__ src,
                              const int* __restrict__ dst,
                              const int* __restrict__ off,
                              int* __restrict__ cur,
                              int* __restrict__ srcs, int E) {
    int e = blockIdx.x * blockDim.x + threadIdx.x;
    if (e >= E) return;
    int s = src[e], d = dst[e];
    int p = off[d] + atomicAdd(&cur[d], 1);
    srcs[p] = s;
}

// ---------------- GEMM: out[N,64] = in[N,K] @ W[K,64] -----------------------
template <int K>
__global__ __launch_bounds__(256)
void gemm_tile(const float* __restrict__ in, const float* __restrict__ W,
               float* __restrict__ out, int N) {
    __shared__ float sx[64 * 36];
    __shared__ float sw[32 * 64];
    int tid = threadIdx.x;
    int tx = tid & 15, ty = tid >> 4;
    int row0 = blockIdx.x * 64;
    float acc[4][4] = {};
    for (int kc = 0; kc < K; kc += 32) {
#pragma unroll
        for (int i = 0; i < 2; i++) {
            int t = tid + i * 256;
            int r = t >> 3, c4 = t & 7;
            int grow = row0 + r;
            float4 v = make_float4(0.f, 0.f, 0.f, 0.f);
            if (grow < N)
                v = *(const float4*)&in[(size_t)grow * K + kc + c4 * 4];
            *(float4*)&sx[r * 36 + c4 * 4] = v;
        }
#pragma unroll
        for (int i = 0; i < 2; i++) {
            int t = tid + i * 256;
            int k = t >> 4, c4 = t & 15;
            *(float4*)&sw[k * 64 + c4 * 4] =
                *(const float4*)&W[(size_t)(kc + k) * 64 + c4 * 4];
        }
        __syncthreads();
#pragma unroll
        for (int k = 0; k < 32; k++) {
            float4 b = *(float4*)&sw[k * 64 + tx * 4];
            float a0 = sx[(ty * 4 + 0) * 36 + k];
            float a1 = sx[(ty * 4 + 1) * 36 + k];
            float a2 = sx[(ty * 4 + 2) * 36 + k];
            float a3 = sx[(ty * 4 + 3) * 36 + k];
            acc[0][0] = fmaf(a0, b.x, acc[0][0]);
            acc[0][1] = fmaf(a0, b.y, acc[0][1]);
            acc[0][2] = fmaf(a0, b.z, acc[0][2]);
            acc[0][3] = fmaf(a0, b.w, acc[0][3]);
            acc[1][0] = fmaf(a1, b.x, acc[1][0]);
            acc[1][1] = fmaf(a1, b.y, acc[1][1]);
            acc[1][2] = fmaf(a1, b.z, acc[1][2]);
            acc[1][3] = fmaf(a1, b.w, acc[1][3]);
            acc[2][0] = fmaf(a2, b.x, acc[2][0]);
            acc[2][1] = fmaf(a2, b.y, acc[2][1]);
            acc[2][2] = fmaf(a2, b.z, acc[2][2]);
            acc[2][3] = fmaf(a2, b.w, acc[2][3]);
            acc[3][0] = fmaf(a3, b.x, acc[3][0]);
            acc[3][1] = fmaf(a3, b.y, acc[3][1]);
            acc[3][2] = fmaf(a3, b.z, acc[3][2]);
            acc[3][3] = fmaf(a3, b.w, acc[3][3]);
        }
        __syncthreads();
    }
#pragma unroll
    for (int i = 0; i < 4; i++) {
        int grow = row0 + ty * 4 + i;
        if (grow < N)
            *(float4*)&out[(size_t)grow * 64 + tx * 4] =
                make_float4(acc[i][0], acc[i][1], acc[i][2], acc[i][3]);
    }
}

// ---------------- fused CSR gather + self-loop + bias + relu -----------------
// one warp per dst node; lane owns 2 feature columns (float2)
__global__ __launch_bounds__(256)
void gather_csr(const int* __restrict__ off, const int* __restrict__ srcs,
                const float* __restrict__ dis, const float* __restrict__ hin,
                float* __restrict__ hout, const float* __restrict__ snorm,
                const float* __restrict__ bias, int N, int do_relu) {
    int w = (blockIdx.x * blockDim.x + threadIdx.x) >> 5;
    int lane = threadIdx.x & 31;
    if (w >= N) return;
    const float2* h2 = (const float2*)hin;
    int s = off[w], e = off[w + 1];
    float dw = dis[w];
    float2 self = h2[(size_t)w * 32 + lane];
    float sn = dw * dw;
    float ax = self.x * sn, ay = self.y * sn;
    int i = s;
    for (; i + 4 <= e; i += 4) {
        int u0 = __ldg(&srcs[i]);
        int u1 = __ldg(&srcs[i + 1]);
        int u2 = __ldg(&srcs[i + 2]);
        int u3 = __ldg(&srcs[i + 3]);
        float n0 = __ldg(&dis[u0]) * dw;
        float n1 = __ldg(&dis[u1]) * dw;
        float n2 = __ldg(&dis[u2]) * dw;
        float n3 = __ldg(&dis[u3]) * dw;
        float2 v0 = h2[(size_t)u0 * 32 + lane];
        float2 v1 = h2[(size_t)u1 * 32 + lane];
        float2 v2 = h2[(size_t)u2 * 32 + lane];
        float2 v3 = h2[(size_t)u3 * 32 + lane];
        ax = fmaf(v0.x, n0, ax); ay = fmaf(v0.y, n0, ay);
        ax = fmaf(v1.x, n1, ax); ay = fmaf(v1.y, n1, ay);
        ax = fmaf(v2.x, n2, ax); ay = fmaf(v2.y, n2, ay);
        ax = fmaf(v3.x, n3, ax); ay = fmaf(v3.y, n3, ay);
    }
    for (; i < e; i++) {
        int u = __ldg(&srcs[i]);
        float n = __ldg(&dis[u]) * dw;
        float2 v = h2[(size_t)u * 32 + lane];
        ax = fmaf(v.x, n, ax); ay = fmaf(v.y, n, ay);
    }
    float2 b = ((const float2*)bias)[lane];
    ax += b.x; ay += b.y;
    if (do_relu) { ax = fmaxf(ax, 0.f); ay = fmaxf(ay, 0.f); }
    ((float2*)hout)[(size_t)w * 32 + lane] = make_float2(ax, ay);
}

// ---------------- pooling + FC -----------------------------------------------
__global__ void pool_sum(const float4* __restrict__ h4,
                         const int* __restrict__ batch,
                         float4* __restrict__ pool4, int N) {
    long long idx = blockIdx.x * (long long)blockDim.x + threadIdx.x;
    if (idx >= (long long)N * 16) return;
    int i = (int)(idx >> 4);
    int c = (int)(idx & 15);
    int g = batch[i];
    red_add_v4(&pool4[(long long)g * 16 + c], h4[idx]);
}

__global__ void pool_cnt(const int* __restrict__ batch,
                         float* __restrict__ cnt, int N) {
    int i = blockIdx.x * blockDim.x + threadIdx.x;
    if (i < N) atomicAdd(&cnt[batch[i]], 1.0f);
}

__global__ void fc_kernel(const float* __restrict__ pool,
                          const float* __restrict__ cnt,
                          const float* __restrict__ Wfc,
                          const float* __restrict__ bfc,
                          float* __restrict__ out) {
    int b = blockIdx.x;
    int t = threadIdx.x;           // 64 threads
    __shared__ float p[HD];
    float inv = 1.0f / fmaxf(cnt[b], 1.0f);
    p[t] = pool[b * HD + t] * inv;
    __syncthreads();
    if (t < NC) {
        float acc = bfc[t];
#pragma unroll
        for (int h = 0; h < HD; h++)
            acc = fmaf(p[h], Wfc[h * NC + t], acc);
        out[b * NC + t] = acc;
    }
}

// ---------------- launch -----------------------------------------------------
extern "C" void kernel_launch(void* const* d_in, const int* in_sizes, int n_in,
                              void* d_out, int out_size) {
    const float* x     = (const float*)d_in[0];
    const int*   ei    = (const int*)d_in[1];     // int32 (JAX x64 disabled)
    const int*   batch = (const int*)d_in[2];
    const float* W1    = (const float*)d_in[3];
    const float* b1    = (const float*)d_in[4];
    const float* W2    = (const float*)d_in[5];
    const float* b2    = (const float*)d_in[6];
    const float* W3    = (const float*)d_in[7];
    const float* b3    = (const float*)d_in[8];
    const float* Wfc   = (const float*)d_in[9];
    const float* bfc   = (const float*)d_in[10];
    float*       out   = (float*)d_out;

    int N = in_sizes[0] / 128;
    int E = in_sizes[1] / 2;
    int B = out_size / NC;

    const int* src = ei;
    const int* dst = ei + E;

    void *p_deg, *p_cur, *p_off, *p_bs, *p_bo, *p_dis, *p_snorm, *p_srcs,
         *p_A, *p_B, *p_pool, *p_cnt;
    cudaGetSymbolAddress(&p_deg, g_deg);
    cudaGetSymbolAddress(&p_cur, g_cur);
    cudaGetSymbolAddress(&p_off, g_off);
    cudaGetSymbolAddress(&p_bs, g_blksum);
    cudaGetSymbolAddress(&p_bo, g_blkoff);
    cudaGetSymbolAddress(&p_dis, g_dis);
    cudaGetSymbolAddress(&p_snorm, g_snorm);
    cudaGetSymbolAddress(&p_srcs, g_srcs);
    cudaGetSymbolAddress(&p_A, g_bufA);
    cudaGetSymbolAddress(&p_B, g_bufB);
    cudaGetSymbolAddress(&p_pool, g_pool);
    cudaGetSymbolAddress(&p_cnt, g_cnt);

    int*    deg   = (int*)p_deg;
    int*    cur   = (int*)p_cur;
    int*    off   = (int*)p_off;
    int*    blks  = (int*)p_bs;
    int*    blko  = (int*)p_bo;
    float*  dis   = (float*)p_dis;
    float*  snorm = (float*)p_snorm;
    int*    srcs  = (int*)p_srcs;
    float*  A     = (float*)p_A;
    float*  Bb    = (float*)p_B;
    float4* B4    = (float4*)p_B;
    float4* pool4 = (float4*)p_pool;
    float*  pool  = (float*)p_pool;
    float*  cnt   = (float*)p_cnt;

    const int T = 256;
    int gEdge = (E + T - 1) / T;
    int gNode = (N + T - 1) / T;
    int gWarp = (int)(((long long)N * 32 + T - 1) / T);
    int gGemm = (N + 63) / 64;
    int nblk  = (N + SCANB - 1) / SCANB;

    // ---- CSR build + norms ----
    cudaMemsetAsync(deg, 0, (size_t)N * sizeof(int));
    cudaMemsetAsync(cur, 0, (size_t)N * sizeof(int));
    deg_count<<<gEdge, T>>>(dst, deg, E);
    node_norms<<<gNode, T>>>(deg, dis, snorm, N);
    scan_p1_reduce<<<nblk, SCANB>>>(deg, blks, N);
    scan_p2_blk<<<1, MAXBLK>>>(blks, blko, off, nblk, N);
    scan_p3_scanadd<<<nblk, SCANB>>>(deg, blko, off, N);
    permute_edges<<<gEdge, T>>>(src, dst, off, cur, srcs, E);

    // ---- layer 1: x(128) -> A -> B ----
    gemm_tile<128><<<gGemm, T>>>(x, W1, A, N);
    gather_csr<<<gWarp, T>>>(off, srcs, dis, A, Bb, snorm, b1, N, 1);

    // ---- layer 2: B -> A -> B ----
    gemm_tile<64><<<gGemm, T>>>(Bb, W2, A, N);
    gather_csr<<<gWarp, T>>>(off, srcs, dis, A, Bb, snorm, b2, N, 1);

    // ---- layer 3: B -> A -> B ----
    gemm_tile<64><<<gGemm, T>>>(Bb, W3, A, N);
    gather_csr<<<gWarp, T>>>(off, srcs, dis, A, Bb, snorm, b3, N, 0);

    // ---- pool + fc ----
    cudaMemsetAsync(pool4, 0, (size_t)B * HD * sizeof(float));
    cudaMemsetAsync(cnt, 0, (size_t)B * sizeof(float));
    pool_sum<<<(int)(((long long)N * 16 + T - 1) / T), T>>>(B4, batch, pool4, N);
    pool_cnt<<<gNode, T>>>(batch, cnt, N);
    fc_kernel<<<B, HD>>>(pool, cnt, Wfc, bfc, out);
}

// round 6
// speedup vs baseline: 2.9104x; 1.0706x over previous
#include <cuda_runtime.h>

#define MAXN  100000
#define MAXE  3200000
#define HD    64
#define NG    512
#define NC    10
#define SCANB 1024
#define MAXBLK 128   // ceil(MAXN/SCANB) = 98

// ---------------- scratch (device globals) ----------------------------------
__device__ int    g_deg[MAXN];
__device__ int    g_cur[MAXN];
__device__ int    g_off[MAXN + 1];
__device__ int    g_blksum[MAXBLK];
__device__ int    g_blkoff[MAXBLK];
__device__ float  g_dis[MAXN];              // 1/sqrt(deg+1)
__device__ int    g_srcs[MAXE];             // src ids, CSR-sorted by dst
__device__ float4 g_bufA[MAXN * HD / 4];
__device__ float4 g_bufB[MAXN * HD / 4];
__device__ float4 g_pool[NG * HD / 4];
__device__ float  g_cnt [NG];

// ---------------- helpers ---------------------------------------------------
__device__ __forceinline__ void red_add_v4(float4* p, float4 v) {
    asm volatile("red.global.add.v4.f32 [%0], {%1,%2,%3,%4};"
                 :: "l"(p), "f"(v.x), "f"(v.y), "f"(v.z), "f"(v.w)
                 : "memory");
}

// ---------------- CSR build --------------------------------------------------
__global__ void deg_count(const int* __restrict__ dst, int* __restrict__ deg,
                          int E) {
    int e = blockIdx.x * blockDim.x + threadIdx.x;
    if (e < E) atomicAdd(&deg[dst[e]], 1);
}

__global__ void node_norms(const int* __restrict__ deg, float* __restrict__ dis,
                           int N) {
    int i = blockIdx.x * blockDim.x + threadIdx.x;
    if (i < N) dis[i] = rsqrtf((float)deg[i] + 1.0f);
}

// ---- 3-phase parallel exclusive scan of deg[0..N) into off[0..N] ----
__global__ void scan_p1_reduce(const int* __restrict__ deg,
                               int* __restrict__ blksum, int N) {
    __shared__ int ws[32];
    int i = blockIdx.x * SCANB + threadIdx.x;
    int v = (i < N) ? deg[i] : 0;
    int lane = threadIdx.x & 31, wid = threadIdx.x >> 5;
#pragma unroll
    for (int o = 16; o > 0; o >>= 1) v += __shfl_down_sync(~0u, v, o);
    if (lane == 0) ws[wid] = v;
    __syncthreads();
    if (wid == 0) {
        int t = ws[lane];
#pragma unroll
        for (int o = 16; o > 0; o >>= 1) t += __shfl_down_sync(~0u, t, o);
        if (lane == 0) blksum[blockIdx.x] = t;
    }
}

__global__ void scan_p2_blk(const int* __restrict__ blksum,
                            int* __restrict__ blkoff,
                            int* __restrict__ off, int nblk, int N) {
    __shared__ int s[MAXBLK];
    int t = threadIdx.x;                        // MAXBLK threads
    s[t] = (t < nblk) ? blksum[t] : 0;
    __syncthreads();
#pragma unroll
    for (int o = 1; o < MAXBLK; o <<= 1) {      // Hillis-Steele inclusive
        int v = (t >= o) ? s[t - o] : 0;
        __syncthreads();
        s[t] += v;
        __syncthreads();
    }
    if (t < nblk) blkoff[t] = s[t] - blksum[t]; // exclusive
    if (t == nblk - 1) off[N] = s[t];           // total
}

__global__ void scan_p3_scanadd(const int* __restrict__ deg,
                                const int* __restrict__ blkoff,
                                int* __restrict__ off, int N) {
    __shared__ int wpre[32];
    int i = blockIdx.x * SCANB + threadIdx.x;
    int v = (i < N) ? deg[i] : 0;
    int lane = threadIdx.x & 31, wid = threadIdx.x >> 5;
    int incl = v;
#pragma unroll
    for (int o = 1; o < 32; o <<= 1) {
        int t = __shfl_up_sync(~0u, incl, o);
        if (lane >= o) incl += t;
    }
    if (lane == 31) wpre[wid] = incl;
    __syncthreads();
    if (wid == 0) {
        int w = wpre[lane];
        int wincl = w;
#pragma unroll
        for (int o = 1; o < 32; o <<= 1) {
            int t = __shfl_up_sync(~0u, wincl, o);
            if (lane >= o) wincl += t;
        }
        wpre[lane] = wincl - w;
    }
    __syncthreads();
    if (i < N) off[i] = blkoff[blockIdx.x] + wpre[wid] + incl - v;
}

// cur[] preloaded with off[]; atomic return carries the base directly.
__global__ void permute_edges(const int* __restrict__ src,
                              const int* __restrict__ dst,
                              int* __restrict__ cur,
                              int* __restrict__ srcs, int E) {
    int e = blockIdx.x * blockDim.x + threadIdx.x;
    if (e >= E) return;
    int s = src[e], d = dst[e];
    int p = atomicAdd(&cur[d], 1);
    srcs[p] = s;
}

// ---------------- GEMM: out[N,64] = in[N,K] @ W[K,64] -----------------------
template <int K>
__global__ __launch_bounds__(256)
void gemm_tile(const float* __restrict__ in, const float* __restrict__ W,
               float* __restrict__ out, int N) {
    __shared__ float sx[64 * 36];
    __shared__ float sw[32 * 64];
    int tid = threadIdx.x;
    int tx = tid & 15, ty = tid >> 4;
    int row0 = blockIdx.x * 64;
    float acc[4][4] = {};
    for (int kc = 0; kc < K; kc += 32) {
#pragma unroll
        for (int i = 0; i < 2; i++) {
            int t = tid + i * 256;
            int r = t >> 3, c4 = t & 7;
            int grow = row0 + r;
            float4 v = make_float4(0.f, 0.f, 0.f, 0.f);
            if (grow < N)
                v = *(const float4*)&in[(size_t)grow * K + kc + c4 * 4];
            *(float4*)&sx[r * 36 + c4 * 4] = v;
        }
#pragma unroll
        for (int i = 0; i < 2; i++) {
            int t = tid + i * 256;
            int k = t >> 4, c4 = t & 15;
            *(float4*)&sw[k * 64 + c4 * 4] =
                *(const float4*)&W[(size_t)(kc + k) * 64 + c4 * 4];
        }
        __syncthreads();
#pragma unroll
        for (int k = 0; k < 32; k++) {
            float4 b = *(float4*)&sw[k * 64 + tx * 4];
            float a0 = sx[(ty * 4 + 0) * 36 + k];
            float a1 = sx[(ty * 4 + 1) * 36 + k];
            float a2 = sx[(ty * 4 + 2) * 36 + k];
            float a3 = sx[(ty * 4 + 3) * 36 + k];
            acc[0][0] = fmaf(a0, b.x, acc[0][0]);
            acc[0][1] = fmaf(a0, b.y, acc[0][1]);
            acc[0][2] = fmaf(a0, b.z, acc[0][2]);
            acc[0][3] = fmaf(a0, b.w, acc[0][3]);
            acc[1][0] = fmaf(a1, b.x, acc[1][0]);
            acc[1][1] = fmaf(a1, b.y, acc[1][1]);
            acc[1][2] = fmaf(a1, b.z, acc[1][2]);
            acc[1][3] = fmaf(a1, b.w, acc[1][3]);
            acc[2][0] = fmaf(a2, b.x, acc[2][0]);
            acc[2][1] = fmaf(a2, b.y, acc[2][1]);
            acc[2][2] = fmaf(a2, b.z, acc[2][2]);
            acc[2][3] = fmaf(a2, b.w, acc[2][3]);
            acc[3][0] = fmaf(a3, b.x, acc[3][0]);
            acc[3][1] = fmaf(a3, b.y, acc[3][1]);
            acc[3][2] = fmaf(a3, b.z, acc[3][2]);
            acc[3][3] = fmaf(a3, b.w, acc[3][3]);
        }
        __syncthreads();
    }
#pragma unroll
    for (int i = 0; i < 4; i++) {
        int grow = row0 + ty * 4 + i;
        if (grow < N)
            *(float4*)&out[(size_t)grow * 64 + tx * 4] =
                make_float4(acc[i][0], acc[i][1], acc[i][2], acc[i][3]);
    }
}

// ---------------- fused CSR gather + self-loop + bias + relu (+pool) ---------
// one warp per dst node; two 16-lane halves each own one edge; lane owns
// 4 consecutive feature columns (float4).
__global__ __launch_bounds__(256)
void gather_csr(const int* __restrict__ off, const int* __restrict__ srcs,
                const float* __restrict__ dis, const float* __restrict__ hin,
                float* __restrict__ hout, const float* __restrict__ bias,
                const int* __restrict__ batch, float4* __restrict__ pool4,
                float* __restrict__ cnt, int N, int do_relu, int do_pool) {
    int w = (blockIdx.x * blockDim.x + threadIdx.x) >> 5;
    int lane = threadIdx.x & 31;
    if (w >= N) return;
    int half = lane >> 4;
    int l16  = lane & 15;
    const float4* h4 = (const float4*)hin;
    int s = off[w], e = off[w + 1];
    float dw = dis[w];
    float4 acc = make_float4(0.f, 0.f, 0.f, 0.f);
    int i = s + half;
    for (; i + 2 < e; i += 4) {                 // 2 edges per half per iter
        int u0 = __ldg(&srcs[i]);
        int u1 = __ldg(&srcs[i + 2]);
        float n0 = __ldg(&dis[u0]) * dw;
        float n1 = __ldg(&dis[u1]) * dw;
        float4 v0 = h4[(size_t)u0 * 16 + l16];
        float4 v1 = h4[(size_t)u1 * 16 + l16];
        acc.x = fmaf(v0.x, n0, acc.x); acc.y = fmaf(v0.y, n0, acc.y);
        acc.z = fmaf(v0.z, n0, acc.z); acc.w = fmaf(v0.w, n0, acc.w);
        acc.x = fmaf(v1.x, n1, acc.x); acc.y = fmaf(v1.y, n1, acc.y);
        acc.z = fmaf(v1.z, n1, acc.z); acc.w = fmaf(v1.w, n1, acc.w);
    }
    for (; i < e; i += 2) {                     // at most one per half
        int u = __ldg(&srcs[i]);
        float n = __ldg(&dis[u]) * dw;
        float4 v = h4[(size_t)u * 16 + l16];
        acc.x = fmaf(v.x, n, acc.x); acc.y = fmaf(v.y, n, acc.y);
        acc.z = fmaf(v.z, n, acc.z); acc.w = fmaf(v.w, n, acc.w);
    }
    // combine the two halves (lane l gets lane l+16's partial)
    acc.x += __shfl_down_sync(~0u, acc.x, 16);
    acc.y += __shfl_down_sync(~0u, acc.y, 16);
    acc.z += __shfl_down_sync(~0u, acc.z, 16);
    acc.w += __shfl_down_sync(~0u, acc.w, 16);
    if (half == 0) {
        float sn = dw * dw;
        float4 self = h4[(size_t)w * 16 + l16];
        float4 b = ((const float4*)bias)[l16];
        acc.x = fmaf(self.x, sn, acc.x) + b.x;
        acc.y = fmaf(self.y, sn, acc.y) + b.y;
        acc.z = fmaf(self.z, sn, acc.z) + b.z;
        acc.w = fmaf(self.w, sn, acc.w) + b.w;
        if (do_relu) {
            acc.x = fmaxf(acc.x, 0.f); acc.y = fmaxf(acc.y, 0.f);
            acc.z = fmaxf(acc.z, 0.f); acc.w = fmaxf(acc.w, 0.f);
        }
        ((float4*)hout)[(size_t)w * 16 + l16] = acc;
        if (do_pool) {
            int g = batch[w];
            red_add_v4(&pool4[(size_t)g * 16 + l16], acc);
            if (l16 == 0) atomicAdd(&cnt[g], 1.0f);
        }
    }
}

// ---------------- FC -----------------------------------------------------
__global__ void fc_kernel(const float* __restrict__ pool,
                          const float* __restrict__ cnt,
                          const float* __restrict__ Wfc,
                          const float* __restrict__ bfc,
                          float* __restrict__ out) {
    int b = blockIdx.x;
    int t = threadIdx.x;           // 64 threads
    __shared__ float p[HD];
    float inv = 1.0f / fmaxf(cnt[b], 1.0f);
    p[t] = pool[b * HD + t] * inv;
    __syncthreads();
    if (t < NC) {
        float acc = bfc[t];
#pragma unroll
        for (int h = 0; h < HD; h++)
            acc = fmaf(p[h], Wfc[h * NC + t], acc);
        out[b * NC + t] = acc;
    }
}

// ---------------- launch -----------------------------------------------------
extern "C" void kernel_launch(void* const* d_in, const int* in_sizes, int n_in,
                              void* d_out, int out_size) {
    const float* x     = (const float*)d_in[0];
    const int*   ei    = (const int*)d_in[1];     // int32 (JAX x64 disabled)
    const int*   batch = (const int*)d_in[2];
    const float* W1    = (const float*)d_in[3];
    const float* b1    = (const float*)d_in[4];
    const float* W2    = (const float*)d_in[5];
    const float* b2    = (const float*)d_in[6];
    const float* W3    = (const float*)d_in[7];
    const float* b3    = (const float*)d_in[8];
    const float* Wfc   = (const float*)d_in[9];
    const float* bfc   = (const float*)d_in[10];
    float*       out   = (float*)d_out;

    int N = in_sizes[0] / 128;
    int E = in_sizes[1] / 2;
    int B = out_size / NC;

    const int* src = ei;
    const int* dst = ei + E;

    void *p_deg, *p_cur, *p_off, *p_bs, *p_bo, *p_dis, *p_srcs,
         *p_A, *p_B, *p_pool, *p_cnt;
    cudaGetSymbolAddress(&p_deg, g_deg);
    cudaGetSymbolAddress(&p_cur, g_cur);
    cudaGetSymbolAddress(&p_off, g_off);
    cudaGetSymbolAddress(&p_bs, g_blksum);
    cudaGetSymbolAddress(&p_bo, g_blkoff);
    cudaGetSymbolAddress(&p_dis, g_dis);
    cudaGetSymbolAddress(&p_srcs, g_srcs);
    cudaGetSymbolAddress(&p_A, g_bufA);
    cudaGetSymbolAddress(&p_B, g_bufB);
    cudaGetSymbolAddress(&p_pool, g_pool);
    cudaGetSymbolAddress(&p_cnt, g_cnt);

    int*    deg   = (int*)p_deg;
    int*    cur   = (int*)p_cur;
    int*    off   = (int*)p_off;
    int*    blks  = (int*)p_bs;
    int*    blko  = (int*)p_bo;
    float*  dis   = (float*)p_dis;
    int*    srcs  = (int*)p_srcs;
    float*  A     = (float*)p_A;
    float*  Bb    = (float*)p_B;
    float4* pool4 = (float4*)p_pool;
    float*  pool  = (float*)p_pool;
    float*  cnt   = (float*)p_cnt;

    const int T = 256;
    int gEdge = (E + T - 1) / T;
    int gNode = (N + T - 1) / T;
    int gWarp = (int)(((long long)N * 32 + T - 1) / T);
    int gGemm = (N + 63) / 64;
    int nblk  = (N + SCANB - 1) / SCANB;

    // ---- CSR build + norms ----
    cudaMemsetAsync(deg, 0, (size_t)N * sizeof(int));
    deg_count<<<gEdge, T>>>(dst, deg, E);
    node_norms<<<gNode, T>>>(deg, dis, N);
    scan_p1_reduce<<<nblk, SCANB>>>(deg, blks, N);
    scan_p2_blk<<<1, MAXBLK>>>(blks, blko, off, nblk, N);
    scan_p3_scanadd<<<nblk, SCANB>>>(deg, blko, off, N);
    cudaMemcpyAsync(cur, off, (size_t)N * sizeof(int), cudaMemcpyDeviceToDevice);
    permute_edges<<<gEdge, T>>>(src, dst, cur, srcs, E);

    // ---- pool buffers (zero early; written only by gather3) ----
    cudaMemsetAsync(pool4, 0, (size_t)B * HD * sizeof(float));
    cudaMemsetAsync(cnt, 0, (size_t)B * sizeof(float));

    // ---- layer 1: x(128) -> A -> B ----
    gemm_tile<128><<<gGemm, T>>>(x, W1, A, N);
    gather_csr<<<gWarp, T>>>(off, srcs, dis, A, Bb, b1, batch, pool4, cnt, N, 1, 0);

    // ---- layer 2: B -> A -> B ----
    gemm_tile<64><<<gGemm, T>>>(Bb, W2, A, N);
    gather_csr<<<gWarp, T>>>(off, srcs, dis, A, Bb, b2, batch, pool4, cnt, N, 1, 0);

    // ---- layer 3: B -> A -> B (+ fused pooling) ----
    gemm_tile<64><<<gGemm, T>>>(Bb, W3, A, N);
    gather_csr<<<gWarp, T>>>(off, srcs, dis, A, Bb, b3, batch, pool4, cnt, N, 0, 1);

    // ---- fc ----
    fc_kernel<<<B, HD>>>(pool, cnt, Wfc, bfc, out);
}